// round 9
// baseline (speedup 1.0000x reference)
#include <cuda_runtime.h>

#define NS 2048
#define ND 2048
#define NK 6

// One warp per (direction, batch) pair. No shared memory, no barriers.
__global__ __launch_bounds__(32, 8)
void query_token_probe_kernel(const float* __restrict__ hs,
                              const float* __restrict__ W,
                              const float* __restrict__ bias,
                              const int*   __restrict__ input_ids,
                              const int*   __restrict__ attn_mask,
                              const int*   __restrict__ token_ids,
                              float*       __restrict__ out) {
    const int kdir = blockIdx.x;   // 0..5
    const int b    = blockIdx.y;   // 0..31
    const int lid  = threadIdx.x;  // 0..31

    const int   tkv = token_ids[kdir];
    const float bk  = bias[kdir];

    // --- Phase 1: warp scans 2048 ids + 2048 mask (16+16 int4 loads/lane, one RT).
    //     Per-j results are INDEPENDENT (4-deep select each), then a 4-level
    //     pairwise max tree: critical chain ~8 links instead of 64. ---
    const int4* __restrict__ mbase = (const int4*)(attn_mask + (size_t)b * NS);
    const int4* __restrict__ ibase = (const int4*)(input_ids + (size_t)b * NS);

    int lvA[16], lmA[16];
#pragma unroll
    for (int j = 0; j < 16; j++) {
        const int4 m4 = mbase[j * 32 + lid];
        const int4 i4 = ibase[j * 32 + lid];
        const int  p0 = (j * 32 + lid) * 4;
        int lvj = -1, lmj = -1;
        // component order x->w: later overwrites earlier == max (positions ascend)
        if (m4.x > 0) { lvj = p0 + 0; if (i4.x == tkv) lmj = p0 + 0; }
        if (m4.y > 0) { lvj = p0 + 1; if (i4.y == tkv) lmj = p0 + 1; }
        if (m4.z > 0) { lvj = p0 + 2; if (i4.z == tkv) lmj = p0 + 2; }
        if (m4.w > 0) { lvj = p0 + 3; if (i4.w == tkv) lmj = p0 + 3; }
        lvA[j] = lvj;
        lmA[j] = lmj;
    }
    // pairwise max tree (levels independent within each stage -> high ILP)
#pragma unroll
    for (int s = 8; s > 0; s >>= 1) {
#pragma unroll
        for (int t = 0; t < s; t++) {
            lvA[t] = max(lvA[t], lvA[t + s]);
            lmA[t] = max(lmA[t], lmA[t + s]);
        }
    }

    const int lastv = __reduce_max_sync(0xffffffffu, lvA[0]);
    int       fp    = __reduce_max_sync(0xffffffffu, lmA[0]);
    if (fp < 0) fp = lastv;
    const int  pos       = fp < 0 ? 0 : (fp > NS - 1 ? NS - 1 : fp);
    const bool has_valid = (lastv >= 0);

    // --- Phase 2: same warp, dot(hs[b,pos,:], W[kdir]); 32 independent loads, one RT ---
    const float4* __restrict__ hrow =
        (const float4*)(hs + ((size_t)b * NS + (size_t)pos) * ND);
    const float4* __restrict__ wrow = (const float4*)(W + (size_t)kdir * ND);

    float s0 = 0.f, s1 = 0.f;
#pragma unroll
    for (int j = 0; j < 16; j += 2) {
        const float4 h0 = hrow[j * 32 + lid];
        const float4 w0 = wrow[j * 32 + lid];
        const float4 h1 = hrow[(j + 1) * 32 + lid];
        const float4 w1 = wrow[(j + 1) * 32 + lid];
        s0 += h0.x * w0.x + h0.y * w0.y + h0.z * w0.z + h0.w * w0.w;
        s1 += h1.x * w1.x + h1.y * w1.y + h1.z * w1.z + h1.w * w1.w;
    }
    float sum = s0 + s1;
#pragma unroll
    for (int off = 16; off > 0; off >>= 1)
        sum += __shfl_xor_sync(0xffffffffu, sum, off);

    if (lid == 0)
        out[b * NK + kdir] = has_valid ? (sum + bk) : 0.f;
}

extern "C" void kernel_launch(void* const* d_in, const int* in_sizes, int n_in,
                              void* d_out, int out_size) {
    const float* hs        = (const float*)d_in[0];
    const float* W         = (const float*)d_in[1];
    const float* bias      = (const float*)d_in[2];
    const int*   input_ids = (const int*)d_in[3];
    const int*   attn_mask = (const int*)d_in[4];
    const int*   token_ids = (const int*)d_in[5];
    float*       out       = (float*)d_out;

    dim3 grid(NK, 32);
    query_token_probe_kernel<<<grid, 32>>>(hs, W, bias, input_ids, attn_mask,
                                           token_ids, out);
}

// round 10
// speedup vs baseline: 1.0093x; 1.0093x over previous
#include <cuda_runtime.h>

#define NS 2048
#define ND 2048
#define NK 6

// One warp per (direction, batch) pair. No shared memory, no barriers.
__global__ __launch_bounds__(32, 8)
void query_token_probe_kernel(const float* __restrict__ hs,
                              const float* __restrict__ W,
                              const float* __restrict__ bias,
                              const int*   __restrict__ input_ids,
                              const int*   __restrict__ attn_mask,
                              const int*   __restrict__ token_ids,
                              float*       __restrict__ out) {
    const int kdir = blockIdx.x;   // 0..5
    const int b    = blockIdx.y;   // 0..31
    const int lid  = threadIdx.x;  // 0..31

    const int   tkv = token_ids[kdir];
    const float bk  = bias[kdir];

    const int4* __restrict__ mbase = (const int4*)(attn_mask + (size_t)b * NS);
    const int4* __restrict__ ibase = (const int4*)(input_ids + (size_t)b * NS);
    const float4* __restrict__ wrow = (const float4*)(W + (size_t)kdir * ND);

    // --- Issue W loads FIRST (position-independent): they ride out the scan's
    //     round trip and are register-resident before phase 2 begins. ---
    float4 wreg[16];
#pragma unroll
    for (int j = 0; j < 16; j++) wreg[j] = wrow[j * 32 + lid];

    // --- Phase 1: scan 2048 ids + 2048 mask (16+16 int4 loads/lane, one RT).
    //     Running overwrite (positions ascend) == running max. ---
    int lv = -1, lm = -1;
#pragma unroll
    for (int j = 0; j < 16; j++) {
        const int4 m4 = mbase[j * 32 + lid];
        const int4 i4 = ibase[j * 32 + lid];
        const int  p0 = (j * 32 + lid) * 4;
        if (m4.x > 0) { lv = p0 + 0; if (i4.x == tkv) lm = p0 + 0; }
        if (m4.y > 0) { lv = p0 + 1; if (i4.y == tkv) lm = p0 + 1; }
        if (m4.z > 0) { lv = p0 + 2; if (i4.z == tkv) lm = p0 + 2; }
        if (m4.w > 0) { lv = p0 + 3; if (i4.w == tkv) lm = p0 + 3; }
    }

    const int lastv = __reduce_max_sync(0xffffffffu, lv);
    int       fp    = __reduce_max_sync(0xffffffffu, lm);
    if (fp < 0) fp = lastv;
    const int  pos       = fp < 0 ? 0 : (fp > NS - 1 ? NS - 1 : fp);
    const bool has_valid = (lastv >= 0);

    // --- Phase 2: only the 16 hs loads remain on the critical path ---
    const float4* __restrict__ hrow =
        (const float4*)(hs + ((size_t)b * NS + (size_t)pos) * ND);

    float s0 = 0.f, s1 = 0.f;
#pragma unroll
    for (int j = 0; j < 16; j += 2) {
        const float4 h0 = hrow[j * 32 + lid];
        const float4 h1 = hrow[(j + 1) * 32 + lid];
        s0 += h0.x * wreg[j].x + h0.y * wreg[j].y + h0.z * wreg[j].z + h0.w * wreg[j].w;
        s1 += h1.x * wreg[j+1].x + h1.y * wreg[j+1].y + h1.z * wreg[j+1].z + h1.w * wreg[j+1].w;
    }
    float sum = s0 + s1;
#pragma unroll
    for (int off = 16; off > 0; off >>= 1)
        sum += __shfl_xor_sync(0xffffffffu, sum, off);

    if (lid == 0)
        out[b * NK + kdir] = has_valid ? (sum + bk) : 0.f;
}

extern "C" void kernel_launch(void* const* d_in, const int* in_sizes, int n_in,
                              void* d_out, int out_size) {
    const float* hs        = (const float*)d_in[0];
    const float* W         = (const float*)d_in[1];
    const float* bias      = (const float*)d_in[2];
    const int*   input_ids = (const int*)d_in[3];
    const int*   attn_mask = (const int*)d_in[4];
    const int*   token_ids = (const int*)d_in[5];
    float*       out       = (float*)d_out;

    dim3 grid(NK, 32);
    query_token_probe_kernel<<<grid, 32>>>(hs, W, bias, input_ids, attn_mask,
                                           token_ids, out);
}

// round 11
// speedup vs baseline: 1.0385x; 1.0288x over previous
#include <cuda_runtime.h>

#define NS 2048
#define ND 2048
#define NK 6

// One warp per (direction, batch) pair. No shared memory, no barriers.
// Issue order matches dependency order: scan loads first, then hs-row loads.
__global__ __launch_bounds__(32, 8)
void query_token_probe_kernel(const float* __restrict__ hs,
                              const float* __restrict__ W,
                              const float* __restrict__ bias,
                              const int*   __restrict__ input_ids,
                              const int*   __restrict__ attn_mask,
                              const int*   __restrict__ token_ids,
                              float*       __restrict__ out) {
    const int kdir = blockIdx.x;   // 0..5
    const int b    = blockIdx.y;   // 0..31
    const int lid  = threadIdx.x;  // 0..31

    const int   tkv = token_ids[kdir];
    const float bk  = bias[kdir];

    // --- Phase 1: whole warp scans 2048 ids + 2048 mask.
    //     16 int4 loads per array per lane, all independent -> one round trip. ---
    const int4* __restrict__ mbase = (const int4*)(attn_mask + (size_t)b * NS);
    const int4* __restrict__ ibase = (const int4*)(input_ids + (size_t)b * NS);

    int lv = -1;   // last valid position seen by this lane
    int lm = -1;   // last position matching tkv

#pragma unroll
    for (int j = 0; j < 16; j++) {
        const int4 m4 = mbase[j * 32 + lid];
        const int4 i4 = ibase[j * 32 + lid];
        const int  p0 = (j * 32 + lid) * 4;
        // positions increase with j and component -> overwrite == running max
        if (m4.x > 0) { lv = p0 + 0; if (i4.x == tkv) lm = p0 + 0; }
        if (m4.y > 0) { lv = p0 + 1; if (i4.y == tkv) lm = p0 + 1; }
        if (m4.z > 0) { lv = p0 + 2; if (i4.z == tkv) lm = p0 + 2; }
        if (m4.w > 0) { lv = p0 + 3; if (i4.w == tkv) lm = p0 + 3; }
    }

    // two single-instruction warp reduces; no barrier needed anywhere
    const int lastv = __reduce_max_sync(0xffffffffu, lv);
    int       fp    = __reduce_max_sync(0xffffffffu, lm);
    if (fp < 0) fp = lastv;
    const int  pos       = fp < 0 ? 0 : (fp > NS - 1 ? NS - 1 : fp);
    const bool has_valid = (lastv >= 0);

    // --- Phase 2: same warp does dot(hs[b,pos,:], W[kdir]).
    //     16 hs + 16 W loads, all independent -> one round trip. ---
    const float4* __restrict__ hrow =
        (const float4*)(hs + ((size_t)b * NS + (size_t)pos) * ND);
    const float4* __restrict__ wrow = (const float4*)(W + (size_t)kdir * ND);

    float s0 = 0.f, s1 = 0.f;
#pragma unroll
    for (int j = 0; j < 16; j += 2) {
        const float4 h0 = hrow[j * 32 + lid];
        const float4 w0 = wrow[j * 32 + lid];
        const float4 h1 = hrow[(j + 1) * 32 + lid];
        const float4 w1 = wrow[(j + 1) * 32 + lid];
        s0 += h0.x * w0.x + h0.y * w0.y + h0.z * w0.z + h0.w * w0.w;
        s1 += h1.x * w1.x + h1.y * w1.y + h1.z * w1.z + h1.w * w1.w;
    }
    float sum = s0 + s1;
#pragma unroll
    for (int off = 16; off > 0; off >>= 1)
        sum += __shfl_xor_sync(0xffffffffu, sum, off);

    if (lid == 0)
        out[b * NK + kdir] = has_valid ? (sum + bk) : 0.f;
}

extern "C" void kernel_launch(void* const* d_in, const int* in_sizes, int n_in,
                              void* d_out, int out_size) {
    const float* hs        = (const float*)d_in[0];
    const float* W         = (const float*)d_in[1];
    const float* bias      = (const float*)d_in[2];
    const int*   input_ids = (const int*)d_in[3];
    const int*   attn_mask = (const int*)d_in[4];
    const int*   token_ids = (const int*)d_in[5];
    float*       out       = (float*)d_out;

    dim3 grid(NK, 32);
    query_token_probe_kernel<<<grid, 32>>>(hs, W, bias, input_ids, attn_mask,
                                           token_ids, out);
}